// round 1
// baseline (speedup 1.0000x reference)
#include <cuda_runtime.h>
#include <math.h>

#define N_ROWS   524288
#define D_IN     64
#define H_DIM    128
#define D_Z      16
#define K_CODES  256
#define TILE_M   128
#define NTHREADS 256
#define NTILES   (N_ROWS / TILE_M)   // 4096

#define AS 132   // AT row stride (floats)
#define CS 132   // CT row stride (floats)

// ---- shared memory layout (float offsets) ----
#define OFF_AT   0
#define SZ_AT    (D_IN * AS)                 // 8448
#define OFF_CT   (OFF_AT + SZ_AT)            // 8448
#define SZ_CT    (H_DIM * CS)                // 16896
#define OFF_WB   (OFF_CT + SZ_CT)            // 25344
#define SZ_WB    (H_DIM * H_DIM)             // 16384
#define OFF_CB   (OFF_WB + SZ_WB)            // 41728
#define SZ_CB    (K_CODES * D_Z)             // 4096
#define OFF_CN   (OFF_CB + SZ_CB)            // 45824
#define OFF_B1   (OFF_CN + 256)              // 46080
#define OFF_B2   (OFF_B1 + 128)              // 46208
#define OFF_BML  (OFF_B2 + 128)              // 46336
#define OFF_MLB  (OFF_BML + 32)              // 46368
#define SZ_MLB   (TILE_M * 33)               // 4224
#define OFF_ZS   (OFF_MLB + SZ_MLB)          // 50592
#define SZ_ZS    (TILE_M * 20)               // 2560
#define OFF_RED  (OFF_ZS + SZ_ZS)            // 53152
#define OFF_REDI (OFF_RED + 256)             // 53408
#define SMEM_FLOATS (OFF_REDI + 256)         // 53664
#define SMEM_BYTES  (SMEM_FLOATS * 4)        // 214656

__device__ float g_partial[NTILES];

__global__ __launch_bounds__(NTHREADS, 1)
void enc_kernel(const float* __restrict__ feats,
                const float* __restrict__ W1,  const float* __restrict__ b1,
                const float* __restrict__ W2,  const float* __restrict__ b2,
                const float* __restrict__ Wmu, const float* __restrict__ bmu,
                const float* __restrict__ Wlv, const float* __restrict__ blv,
                const float* __restrict__ codebook, const float* __restrict__ eps,
                float* __restrict__ outZ,  float* __restrict__ outMu,
                float* __restrict__ outLv, float* __restrict__ outZq)
{
    extern __shared__ float sm[];
    const int tid = threadIdx.x;
    const int tx  = tid & 15;
    const int ty  = tid >> 4;
    const int tile = blockIdx.x;
    const int row0 = tile * TILE_M;

    float* AT   = sm + OFF_AT;
    float* CT   = sm + OFF_CT;
    float* WB   = sm + OFF_WB;
    float* CBs  = sm + OFF_CB;
    float* CNs  = sm + OFF_CN;
    float* B1s  = sm + OFF_B1;
    float* B2s  = sm + OFF_B2;
    float* BMLs = sm + OFF_BML;
    float* MLB  = sm + OFF_MLB;
    float* ZS   = sm + OFF_ZS;
    float* REDs = sm + OFF_RED;
    int*   REDi = (int*)(sm + OFF_REDI);

    // ---------- stage 0: load X (transposed), W1, codebook, biases ----------
    {
        const float4* Xg = (const float4*)(feats + (size_t)row0 * D_IN);
        #pragma unroll
        for (int it = 0; it < 8; ++it) {
            int i = tid + it * NTHREADS;     // 0..2047 float4s
            float4 v = Xg[i];
            int r  = i >> 4;                 // row within tile
            int k0 = (i & 15) << 2;          // starting k
            AT[(k0+0)*AS + r] = v.x;
            AT[(k0+1)*AS + r] = v.y;
            AT[(k0+2)*AS + r] = v.z;
            AT[(k0+3)*AS + r] = v.w;
        }
        const float4* w1 = (const float4*)W1;     // 64*128 = 2048 f4
        #pragma unroll
        for (int it = 0; it < 8; ++it)
            ((float4*)WB)[tid + it*NTHREADS] = w1[tid + it*NTHREADS];
        const float4* cb4 = (const float4*)codebook;  // 256*16 = 1024 f4
        #pragma unroll
        for (int it = 0; it < 4; ++it)
            ((float4*)CBs)[tid + it*NTHREADS] = cb4[tid + it*NTHREADS];
        if (tid < 128) { B1s[tid] = b1[tid]; B2s[tid] = b2[tid]; }
        if (tid < 16)  { BMLs[tid] = bmu[tid]; BMLs[16+tid] = blv[tid]; }
    }
    __syncthreads();

    // codebook norms (one code per thread); consumed only after later syncs
    {
        const float4* c4 = (const float4*)(CBs + tid * D_Z);
        float4 q0 = c4[0], q1 = c4[1], q2 = c4[2], q3 = c4[3];
        float s = q0.x*q0.x + q0.y*q0.y + q0.z*q0.z + q0.w*q0.w
                + q1.x*q1.x + q1.y*q1.y + q1.z*q1.z + q1.w*q1.w
                + q2.x*q2.x + q2.y*q2.y + q2.z*q2.z + q2.w*q2.w
                + q3.x*q3.x + q3.y*q3.y + q3.z*q3.z + q3.w*q3.w;
        CNs[tid] = s;
    }

    const int r0 = ty * 8;
    const int cA = tx * 4;
    const int cB = 64 + tx * 4;

    float acc[8][8];
    #pragma unroll
    for (int i = 0; i < 8; ++i)
        #pragma unroll
        for (int j = 0; j < 8; ++j) acc[i][j] = 0.f;

    // ---------- GEMM1: h1 = relu(X @ W1 + b1) ----------
    #pragma unroll 4
    for (int k = 0; k < D_IN; ++k) {
        float4 a0 = *(const float4*)(AT + k*AS + r0);
        float4 a1 = *(const float4*)(AT + k*AS + r0 + 4);
        float4 b0 = *(const float4*)(WB + k*H_DIM + cA);
        float4 b1v= *(const float4*)(WB + k*H_DIM + cB);
        float av[8] = {a0.x,a0.y,a0.z,a0.w,a1.x,a1.y,a1.z,a1.w};
        float bv[8] = {b0.x,b0.y,b0.z,b0.w,b1v.x,b1v.y,b1v.z,b1v.w};
        #pragma unroll
        for (int i = 0; i < 8; ++i)
            #pragma unroll
            for (int j = 0; j < 8; ++j)
                acc[i][j] = fmaf(av[i], bv[j], acc[i][j]);
    }
    // epilogue: relu(acc + b1) -> CT (stored transposed: CT[col][row])
    #pragma unroll
    for (int j = 0; j < 8; ++j) {
        int c = (j < 4) ? (cA + j) : (cB + j - 4);
        float bias = B1s[c];
        float4 v0 = make_float4(fmaxf(acc[0][j]+bias,0.f), fmaxf(acc[1][j]+bias,0.f),
                                fmaxf(acc[2][j]+bias,0.f), fmaxf(acc[3][j]+bias,0.f));
        float4 v1 = make_float4(fmaxf(acc[4][j]+bias,0.f), fmaxf(acc[5][j]+bias,0.f),
                                fmaxf(acc[6][j]+bias,0.f), fmaxf(acc[7][j]+bias,0.f));
        *(float4*)(CT + c*CS + r0)     = v0;
        *(float4*)(CT + c*CS + r0 + 4) = v1;
    }
    __syncthreads();

    // load W2 (overwrites W1)
    {
        const float4* w2 = (const float4*)W2;    // 128*128 = 4096 f4
        #pragma unroll
        for (int it = 0; it < 16; ++it)
            ((float4*)WB)[tid + it*NTHREADS] = w2[tid + it*NTHREADS];
    }
    __syncthreads();

    // ---------- GEMM2: h2 = relu(h1 @ W2 + b2) ----------
    #pragma unroll
    for (int i = 0; i < 8; ++i)
        #pragma unroll
        for (int j = 0; j < 8; ++j) acc[i][j] = 0.f;

    #pragma unroll 4
    for (int k = 0; k < H_DIM; ++k) {
        float4 a0 = *(const float4*)(CT + k*CS + r0);
        float4 a1 = *(const float4*)(CT + k*CS + r0 + 4);
        float4 b0 = *(const float4*)(WB + k*H_DIM + cA);
        float4 b1v= *(const float4*)(WB + k*H_DIM + cB);
        float av[8] = {a0.x,a0.y,a0.z,a0.w,a1.x,a1.y,a1.z,a1.w};
        float bv[8] = {b0.x,b0.y,b0.z,b0.w,b1v.x,b1v.y,b1v.z,b1v.w};
        #pragma unroll
        for (int i = 0; i < 8; ++i)
            #pragma unroll
            for (int j = 0; j < 8; ++j)
                acc[i][j] = fmaf(av[i], bv[j], acc[i][j]);
    }
    __syncthreads();   // all reads of CT(h1) + WB(W2) done

    // epilogue: h2 -> CT (overwrite); load Wmu|Wlv -> WB[k*32 + c]
    #pragma unroll
    for (int j = 0; j < 8; ++j) {
        int c = (j < 4) ? (cA + j) : (cB + j - 4);
        float bias = B2s[c];
        float4 v0 = make_float4(fmaxf(acc[0][j]+bias,0.f), fmaxf(acc[1][j]+bias,0.f),
                                fmaxf(acc[2][j]+bias,0.f), fmaxf(acc[3][j]+bias,0.f));
        float4 v1 = make_float4(fmaxf(acc[4][j]+bias,0.f), fmaxf(acc[5][j]+bias,0.f),
                                fmaxf(acc[6][j]+bias,0.f), fmaxf(acc[7][j]+bias,0.f));
        *(float4*)(CT + c*CS + r0)     = v0;
        *(float4*)(CT + c*CS + r0 + 4) = v1;
    }
    {
        #pragma unroll
        for (int it = 0; it < 2; ++it) {
            int i = tid + it*NTHREADS;          // 0..511 f4 (128*16 floats)
            float4 v = ((const float4*)Wmu)[i];
            float4 u = ((const float4*)Wlv)[i];
            int k  = i >> 2;
            int c0 = (i & 3) << 2;
            *(float4*)(WB + k*32 + c0)      = v;
            *(float4*)(WB + k*32 + 16 + c0) = u;
        }
    }
    __syncthreads();

    // ---------- GEMM3: [mu | lv] = h2 @ [Wmu | Wlv] + [bmu | blv] ----------
    float acc3[8][2];
    #pragma unroll
    for (int i = 0; i < 8; ++i) { acc3[i][0] = 0.f; acc3[i][1] = 0.f; }

    const int c3 = 2 * tx;
    #pragma unroll 4
    for (int k = 0; k < H_DIM; ++k) {
        float4 a0 = *(const float4*)(CT + k*CS + r0);
        float4 a1 = *(const float4*)(CT + k*CS + r0 + 4);
        float w0 = WB[k*32 + c3];
        float w1v= WB[k*32 + c3 + 1];
        float av[8] = {a0.x,a0.y,a0.z,a0.w,a1.x,a1.y,a1.z,a1.w};
        #pragma unroll
        for (int i = 0; i < 8; ++i) {
            acc3[i][0] = fmaf(av[i], w0,  acc3[i][0]);
            acc3[i][1] = fmaf(av[i], w1v, acc3[i][1]);
        }
    }
    // epilogue: write mu/lv to smem MLB and to global
    #pragma unroll
    for (int j = 0; j < 2; ++j) {
        int c = c3 + j;
        float bias = BMLs[c];
        float* gout = (c < D_Z) ? (outMu + c) : (outLv + (c - D_Z));
        #pragma unroll
        for (int i = 0; i < 8; ++i) {
            float v = acc3[i][j] + bias;
            MLB[(r0 + i)*33 + c] = v;
            gout[(size_t)(row0 + r0 + i) * D_Z] = v;
        }
    }
    __syncthreads();

    // ---------- z = mu + eps * exp(0.5*lv) ----------
    {
        int row = tid >> 1;
        int d0  = (tid & 1) << 3;
        size_t g = (size_t)(row0 + row) * D_Z + d0;
        float4 e0 = *(const float4*)(eps + g);
        float4 e1 = *(const float4*)(eps + g + 4);
        float ev[8] = {e0.x,e0.y,e0.z,e0.w,e1.x,e1.y,e1.z,e1.w};
        float zv[8];
        #pragma unroll
        for (int q = 0; q < 8; ++q) {
            float mu = MLB[row*33 + d0 + q];
            float lv = MLB[row*33 + 16 + d0 + q];
            zv[q] = fmaf(ev[q], expf(0.5f * lv), mu);
        }
        *(float4*)(ZS + row*20 + d0)     = make_float4(zv[0],zv[1],zv[2],zv[3]);
        *(float4*)(ZS + row*20 + d0 + 4) = make_float4(zv[4],zv[5],zv[6],zv[7]);
        *(float4*)(outZ + g)     = make_float4(zv[0],zv[1],zv[2],zv[3]);
        *(float4*)(outZ + g + 4) = make_float4(zv[4],zv[5],zv[6],zv[7]);
    }
    __syncthreads();

    // ---------- VQ argmin: score = |c|^2 - 2 z.c (|z|^2 constant per row) ----------
    {
        int row  = tid & 127;
        int half = tid >> 7;
        float4 z0 = *(const float4*)(ZS + row*20);
        float4 z1 = *(const float4*)(ZS + row*20 + 4);
        float4 z2 = *(const float4*)(ZS + row*20 + 8);
        float4 z3 = *(const float4*)(ZS + row*20 + 12);
        float best = 3.4e38f;
        int   bi   = 0;
        int cbase = half << 7;
        for (int c = 0; c < 128; ++c) {
            const float4* q = (const float4*)(CBs + (cbase + c) * D_Z);
            float4 q0 = q[0], q1 = q[1], q2 = q[2], q3 = q[3];
            float dot = z0.x*q0.x;
            dot = fmaf(z0.y, q0.y, dot); dot = fmaf(z0.z, q0.z, dot); dot = fmaf(z0.w, q0.w, dot);
            dot = fmaf(z1.x, q1.x, dot); dot = fmaf(z1.y, q1.y, dot); dot = fmaf(z1.z, q1.z, dot); dot = fmaf(z1.w, q1.w, dot);
            dot = fmaf(z2.x, q2.x, dot); dot = fmaf(z2.y, q2.y, dot); dot = fmaf(z2.z, q2.z, dot); dot = fmaf(z2.w, q2.w, dot);
            dot = fmaf(z3.x, q3.x, dot); dot = fmaf(z3.y, q3.y, dot); dot = fmaf(z3.z, q3.z, dot); dot = fmaf(z3.w, q3.w, dot);
            float score = fmaf(-2.f, dot, CNs[cbase + c]);
            if (score < best) { best = score; bi = cbase + c; }
        }
        REDs[tid] = best;
        REDi[tid] = bi;
    }
    __syncthreads();

    float ss = 0.f;
    if (tid < 128) {
        int row = tid;
        float lo = REDs[tid];
        int idx = (REDs[tid + 128] < lo) ? REDi[tid + 128] : REDi[tid];
        size_t g = (size_t)(row0 + row) * D_Z;
        #pragma unroll
        for (int q4 = 0; q4 < 4; ++q4) {
            float4 qc = *(const float4*)(CBs + idx*D_Z + q4*4);
            float4 zz = *(const float4*)(ZS + row*20 + q4*4);
            float d0 = qc.x - zz.x, d1 = qc.y - zz.y, d2 = qc.z - zz.z, d3 = qc.w - zz.w;
            ss = fmaf(d0, d0, ss); ss = fmaf(d1, d1, ss);
            ss = fmaf(d2, d2, ss); ss = fmaf(d3, d3, ss);
            *(float4*)(outZq + g + q4*4) = qc;
        }
    }
    __syncthreads();
    if (tid < 128) REDs[tid] = ss;
    __syncthreads();
    #pragma unroll
    for (int s = 64; s > 0; s >>= 1) {
        if (tid < s) REDs[tid] += REDs[tid + s];
        __syncthreads();
    }
    if (tid == 0) g_partial[tile] = REDs[0];
}

__global__ void loss_kernel(float* __restrict__ out_loss)
{
    __shared__ float s[256];
    float v = 0.f;
    for (int i = threadIdx.x; i < NTILES; i += 256) v += g_partial[i];
    s[threadIdx.x] = v;
    __syncthreads();
    #pragma unroll
    for (int st = 128; st > 0; st >>= 1) {
        if (threadIdx.x < st) s[threadIdx.x] += s[threadIdx.x + st];
        __syncthreads();
    }
    if (threadIdx.x == 0) {
        float m = s[0] / (float)((long long)N_ROWS * D_Z);
        out_loss[0] = 0.25f * (m + m);   // BETA * (loss_commit + loss_code)
    }
}

extern "C" void kernel_launch(void* const* d_in, const int* in_sizes, int n_in,
                              void* d_out, int out_size)
{
    const float* feats    = (const float*)d_in[0];
    const float* W1       = (const float*)d_in[1];
    const float* b1       = (const float*)d_in[2];
    const float* W2       = (const float*)d_in[3];
    const float* b2       = (const float*)d_in[4];
    const float* Wmu      = (const float*)d_in[5];
    const float* bmu      = (const float*)d_in[6];
    const float* Wlv      = (const float*)d_in[7];
    const float* blv      = (const float*)d_in[8];
    const float* codebook = (const float*)d_in[9];
    const float* eps      = (const float*)d_in[10];

    float* out = (float*)d_out;
    size_t sec = (size_t)N_ROWS * D_Z;

    cudaFuncSetAttribute(enc_kernel, cudaFuncAttributeMaxDynamicSharedMemorySize, SMEM_BYTES);

    enc_kernel<<<NTILES, NTHREADS, SMEM_BYTES>>>(
        feats, W1, b1, W2, b2, Wmu, bmu, Wlv, blv, codebook, eps,
        out,                // z
        out + sec,          // mu
        out + 2 * sec,      // lv
        out + 3 * sec);     // z_q

    loss_kernel<<<1, 256>>>(out + 4 * sec);
}

// round 2
// speedup vs baseline: 1.1099x; 1.1099x over previous
#include <cuda_runtime.h>
#include <math.h>

#define N_ROWS   524288
#define D_IN     64
#define H_DIM    128
#define D_Z      16
#define K_CODES  256
#define TILE_M   128
#define NTHREADS 256
#define NTILES   (N_ROWS / TILE_M)   // 4096

#define AS 132   // AT row stride (floats)
#define CS 132   // CT row stride (floats)

// ---- shared memory layout (float offsets) ----
#define OFF_AT   0
#define SZ_AT    (D_IN * AS)                 // 8448
#define OFF_CT   (OFF_AT + SZ_AT)            // 8448
#define SZ_CT    (H_DIM * CS)                // 16896
#define OFF_WB   (OFF_CT + SZ_CT)            // 25344
#define SZ_WB    (H_DIM * H_DIM)             // 16384
#define OFF_CB   (OFF_WB + SZ_WB)            // 41728
#define SZ_CB    (K_CODES * D_Z)             // 4096
#define OFF_CN   (OFF_CB + SZ_CB)            // 45824
#define OFF_B1   (OFF_CN + 256)              // 46080
#define OFF_B2   (OFF_B1 + 128)              // 46208
#define OFF_BML  (OFF_B2 + 128)              // 46336
#define OFF_MLB  (OFF_BML + 32)              // 46368
#define SZ_MLB   (TILE_M * 33)               // 4224
#define OFF_ZS   (OFF_MLB + SZ_MLB)          // 50592
#define SZ_ZS    (TILE_M * 20)               // 2560
#define OFF_RED  (OFF_ZS + SZ_ZS)            // 53152
#define OFF_REDI (OFF_RED + 256)             // 53408
#define SMEM_FLOATS (OFF_REDI + 256)         // 53664
#define SMEM_BYTES  (SMEM_FLOATS * 4)        // 214656

typedef unsigned long long u64;

__device__ __forceinline__ u64 bcast2(float x) {
    u64 r; asm("mov.b64 %0, {%1, %1};" : "=l"(r) : "f"(x)); return r;
}
__device__ __forceinline__ u64 pack2(float x, float y) {
    u64 r; asm("mov.b64 %0, {%1, %2};" : "=l"(r) : "f"(x), "f"(y)); return r;
}
__device__ __forceinline__ void unpack2(u64 v, float& x, float& y) {
    asm("mov.b64 {%0, %1}, %2;" : "=f"(x), "=f"(y) : "l"(v));
}
__device__ __forceinline__ void fma2(u64& d, u64 a, u64 b) {
    asm("fma.rn.f32x2 %0, %1, %2, %3;" : "=l"(d) : "l"(a), "l"(b), "l"(d));
}

__device__ float g_partial[NTILES];

__global__ __launch_bounds__(NTHREADS, 1)
void enc_kernel(const float* __restrict__ feats,
                const float* __restrict__ W1,  const float* __restrict__ b1,
                const float* __restrict__ W2,  const float* __restrict__ b2,
                const float* __restrict__ Wmu, const float* __restrict__ bmu,
                const float* __restrict__ Wlv, const float* __restrict__ blv,
                const float* __restrict__ codebook, const float* __restrict__ eps,
                float* __restrict__ outZ,  float* __restrict__ outMu,
                float* __restrict__ outLv, float* __restrict__ outZq)
{
    extern __shared__ float sm[];
    const int tid = threadIdx.x;
    const int tx  = tid & 15;
    const int ty  = tid >> 4;
    const int tile = blockIdx.x;
    const int row0 = tile * TILE_M;

    float* AT   = sm + OFF_AT;
    float* CT   = sm + OFF_CT;
    float* WB   = sm + OFF_WB;
    float* CBs  = sm + OFF_CB;
    float* CNs  = sm + OFF_CN;
    float* B1s  = sm + OFF_B1;
    float* B2s  = sm + OFF_B2;
    float* BMLs = sm + OFF_BML;
    float* MLB  = sm + OFF_MLB;
    float* ZS   = sm + OFF_ZS;
    float* REDs = sm + OFF_RED;
    int*   REDi = (int*)(sm + OFF_REDI);

    // ---------- stage 0: load X (transposed), W1, codebook, biases ----------
    {
        const float4* Xg = (const float4*)(feats + (size_t)row0 * D_IN);
        #pragma unroll
        for (int it = 0; it < 8; ++it) {
            int i = tid + it * NTHREADS;     // 0..2047 float4s
            float4 v = Xg[i];
            int r  = i >> 4;                 // row within tile
            int k0 = (i & 15) << 2;          // starting k
            AT[(k0+0)*AS + r] = v.x;
            AT[(k0+1)*AS + r] = v.y;
            AT[(k0+2)*AS + r] = v.z;
            AT[(k0+3)*AS + r] = v.w;
        }
        const float4* w1 = (const float4*)W1;     // 64*128 = 2048 f4
        #pragma unroll
        for (int it = 0; it < 8; ++it)
            ((float4*)WB)[tid + it*NTHREADS] = w1[tid + it*NTHREADS];
        const float4* cb4 = (const float4*)codebook;  // 256*16 = 1024 f4
        #pragma unroll
        for (int it = 0; it < 4; ++it)
            ((float4*)CBs)[tid + it*NTHREADS] = cb4[tid + it*NTHREADS];
        if (tid < 128) { B1s[tid] = b1[tid]; B2s[tid] = b2[tid]; }
        if (tid < 16)  { BMLs[tid] = bmu[tid]; BMLs[16+tid] = blv[tid]; }
    }
    __syncthreads();

    // codebook norms (one code per thread); consumed only after later syncs
    {
        const float4* c4 = (const float4*)(CBs + tid * D_Z);
        float4 q0 = c4[0], q1 = c4[1], q2 = c4[2], q3 = c4[3];
        float s = q0.x*q0.x + q0.y*q0.y + q0.z*q0.z + q0.w*q0.w
                + q1.x*q1.x + q1.y*q1.y + q1.z*q1.z + q1.w*q1.w
                + q2.x*q2.x + q2.y*q2.y + q2.z*q2.z + q2.w*q2.w
                + q3.x*q3.x + q3.y*q3.y + q3.z*q3.z + q3.w*q3.w;
        CNs[tid] = s;
    }

    const int r0 = ty * 8;
    const int cA = tx * 4;
    const int cB = 64 + tx * 4;

    // packed accumulators: acc2[i][jp] = cols {pair} for row r0+i
    // jp: 0 -> (cA,cA+1), 1 -> (cA+2,cA+3), 2 -> (cB,cB+1), 3 -> (cB+2,cB+3)
    u64 acc2[8][4];
    #pragma unroll
    for (int i = 0; i < 8; ++i)
        #pragma unroll
        for (int j = 0; j < 4; ++j) acc2[i][j] = 0ULL;

    // ---------- GEMM1: h1 = relu(X @ W1 + b1) ----------
    #pragma unroll 4
    for (int k = 0; k < D_IN; ++k) {
        float4 a0 = *(const float4*)(AT + k*AS + r0);
        float4 a1 = *(const float4*)(AT + k*AS + r0 + 4);
        ulonglong2 bq0 = *(const ulonglong2*)(WB + k*H_DIM + cA);
        ulonglong2 bq1 = *(const ulonglong2*)(WB + k*H_DIM + cB);
        u64 bp0 = bq0.x, bp1 = bq0.y, bp2 = bq1.x, bp3 = bq1.y;
        float av[8] = {a0.x,a0.y,a0.z,a0.w,a1.x,a1.y,a1.z,a1.w};
        #pragma unroll
        for (int i = 0; i < 8; ++i) {
            u64 aa = bcast2(av[i]);
            fma2(acc2[i][0], aa, bp0);
            fma2(acc2[i][1], aa, bp1);
            fma2(acc2[i][2], aa, bp2);
            fma2(acc2[i][3], aa, bp3);
        }
    }
    // epilogue: relu(acc + b1) -> CT (stored transposed: CT[col][row])
    #pragma unroll
    for (int jp = 0; jp < 4; ++jp) {
        int c0 = (jp < 2) ? (cA + 2*jp) : (cB + 2*(jp-2));
        float bias0 = B1s[c0], bias1 = B1s[c0+1];
        float v0[8], v1[8];
        #pragma unroll
        for (int i = 0; i < 8; ++i) {
            float x, y; unpack2(acc2[i][jp], x, y);
            v0[i] = fmaxf(x + bias0, 0.f);
            v1[i] = fmaxf(y + bias1, 0.f);
        }
        *(float4*)(CT + c0*CS + r0)       = make_float4(v0[0],v0[1],v0[2],v0[3]);
        *(float4*)(CT + c0*CS + r0 + 4)   = make_float4(v0[4],v0[5],v0[6],v0[7]);
        *(float4*)(CT + (c0+1)*CS + r0)     = make_float4(v1[0],v1[1],v1[2],v1[3]);
        *(float4*)(CT + (c0+1)*CS + r0 + 4) = make_float4(v1[4],v1[5],v1[6],v1[7]);
    }
    __syncthreads();

    // load W2 (overwrites W1)
    {
        const float4* w2 = (const float4*)W2;    // 128*128 = 4096 f4
        #pragma unroll
        for (int it = 0; it < 16; ++it)
            ((float4*)WB)[tid + it*NTHREADS] = w2[tid + it*NTHREADS];
    }
    __syncthreads();

    // ---------- GEMM2: h2 = relu(h1 @ W2 + b2) ----------
    #pragma unroll
    for (int i = 0; i < 8; ++i)
        #pragma unroll
        for (int j = 0; j < 4; ++j) acc2[i][j] = 0ULL;

    #pragma unroll 4
    for (int k = 0; k < H_DIM; ++k) {
        float4 a0 = *(const float4*)(CT + k*CS + r0);
        float4 a1 = *(const float4*)(CT + k*CS + r0 + 4);
        ulonglong2 bq0 = *(const ulonglong2*)(WB + k*H_DIM + cA);
        ulonglong2 bq1 = *(const ulonglong2*)(WB + k*H_DIM + cB);
        u64 bp0 = bq0.x, bp1 = bq0.y, bp2 = bq1.x, bp3 = bq1.y;
        float av[8] = {a0.x,a0.y,a0.z,a0.w,a1.x,a1.y,a1.z,a1.w};
        #pragma unroll
        for (int i = 0; i < 8; ++i) {
            u64 aa = bcast2(av[i]);
            fma2(acc2[i][0], aa, bp0);
            fma2(acc2[i][1], aa, bp1);
            fma2(acc2[i][2], aa, bp2);
            fma2(acc2[i][3], aa, bp3);
        }
    }
    __syncthreads();   // all reads of CT(h1) + WB(W2) done

    // epilogue: h2 -> CT (overwrite); load Wmu|Wlv -> WB[k*32 + c]
    #pragma unroll
    for (int jp = 0; jp < 4; ++jp) {
        int c0 = (jp < 2) ? (cA + 2*jp) : (cB + 2*(jp-2));
        float bias0 = B2s[c0], bias1 = B2s[c0+1];
        float v0[8], v1[8];
        #pragma unroll
        for (int i = 0; i < 8; ++i) {
            float x, y; unpack2(acc2[i][jp], x, y);
            v0[i] = fmaxf(x + bias0, 0.f);
            v1[i] = fmaxf(y + bias1, 0.f);
        }
        *(float4*)(CT + c0*CS + r0)       = make_float4(v0[0],v0[1],v0[2],v0[3]);
        *(float4*)(CT + c0*CS + r0 + 4)   = make_float4(v0[4],v0[5],v0[6],v0[7]);
        *(float4*)(CT + (c0+1)*CS + r0)     = make_float4(v1[0],v1[1],v1[2],v1[3]);
        *(float4*)(CT + (c0+1)*CS + r0 + 4) = make_float4(v1[4],v1[5],v1[6],v1[7]);
    }
    {
        #pragma unroll
        for (int it = 0; it < 2; ++it) {
            int i = tid + it*NTHREADS;          // 0..511 f4 (128*16 floats)
            float4 v = ((const float4*)Wmu)[i];
            float4 u = ((const float4*)Wlv)[i];
            int k  = i >> 2;
            int c0 = (i & 3) << 2;
            *(float4*)(WB + k*32 + c0)      = v;
            *(float4*)(WB + k*32 + 16 + c0) = u;
        }
    }
    __syncthreads();

    // ---------- GEMM3: [mu | lv] = h2 @ [Wmu | Wlv] + [bmu | blv] ----------
    u64 acc3[8];
    #pragma unroll
    for (int i = 0; i < 8; ++i) acc3[i] = 0ULL;

    const int c3 = 2 * tx;   // even -> 8-byte aligned pair in WB
    #pragma unroll 4
    for (int k = 0; k < H_DIM; ++k) {
        float4 a0 = *(const float4*)(CT + k*CS + r0);
        float4 a1 = *(const float4*)(CT + k*CS + r0 + 4);
        u64 wp = *(const u64*)(WB + k*32 + c3);
        float av[8] = {a0.x,a0.y,a0.z,a0.w,a1.x,a1.y,a1.z,a1.w};
        #pragma unroll
        for (int i = 0; i < 8; ++i) {
            u64 aa = bcast2(av[i]);
            fma2(acc3[i], aa, wp);
        }
    }
    // epilogue: write mu/lv to smem MLB and to global
    {
        float bias0 = BMLs[c3], bias1 = BMLs[c3 + 1];
        float* g0 = (c3 < D_Z) ? (outMu + c3) : (outLv + (c3 - D_Z));
        float* g1 = (c3 + 1 < D_Z) ? (outMu + c3 + 1) : (outLv + (c3 + 1 - D_Z));
        #pragma unroll
        for (int i = 0; i < 8; ++i) {
            float x, y; unpack2(acc3[i], x, y);
            x += bias0; y += bias1;
            MLB[(r0 + i)*33 + c3]     = x;
            MLB[(r0 + i)*33 + c3 + 1] = y;
            g0[(size_t)(row0 + r0 + i) * D_Z] = x;
            g1[(size_t)(row0 + r0 + i) * D_Z] = y;
        }
    }
    __syncthreads();

    // ---------- z = mu + eps * exp(0.5*lv) ----------
    {
        int row = tid >> 1;
        int d0  = (tid & 1) << 3;
        size_t g = (size_t)(row0 + row) * D_Z + d0;
        float4 e0 = *(const float4*)(eps + g);
        float4 e1 = *(const float4*)(eps + g + 4);
        float ev[8] = {e0.x,e0.y,e0.z,e0.w,e1.x,e1.y,e1.z,e1.w};
        float zv[8];
        #pragma unroll
        for (int q = 0; q < 8; ++q) {
            float mu = MLB[row*33 + d0 + q];
            float lv = MLB[row*33 + 16 + d0 + q];
            zv[q] = fmaf(ev[q], expf(0.5f * lv), mu);
        }
        *(float4*)(ZS + row*20 + d0)     = make_float4(zv[0],zv[1],zv[2],zv[3]);
        *(float4*)(ZS + row*20 + d0 + 4) = make_float4(zv[4],zv[5],zv[6],zv[7]);
        *(float4*)(outZ + g)     = make_float4(zv[0],zv[1],zv[2],zv[3]);
        *(float4*)(outZ + g + 4) = make_float4(zv[4],zv[5],zv[6],zv[7]);
    }
    __syncthreads();

    // ---------- VQ argmin: score = |c|^2 - 2 z.c (|z|^2 constant per row) ----------
    {
        int row  = tid & 127;
        int half = tid >> 7;
        // z as 8 packed pairs (ZS row base is 8-byte aligned: 20 floats stride)
        u64 zp[8];
        #pragma unroll
        for (int q = 0; q < 8; ++q)
            zp[q] = *(const u64*)(ZS + row*20 + 2*q);
        float best = 3.4e38f;
        int   bi   = 0;
        int cbase = half << 7;
        for (int c = 0; c < 128; ++c) {
            const ulonglong2* q2 = (const ulonglong2*)(CBs + (cbase + c) * D_Z);
            ulonglong2 qa = q2[0], qb = q2[1];
            u64 dp = 0ULL;
            fma2(dp, zp[0], qa.x);
            fma2(dp, zp[1], qa.y);
            fma2(dp, zp[2], qb.x);
            fma2(dp, zp[3], qb.y);
            ulonglong2 qc = q2[2], qd = q2[3];
            fma2(dp, zp[4], qc.x);
            fma2(dp, zp[5], qc.y);
            fma2(dp, zp[6], qd.x);
            fma2(dp, zp[7], qd.y);
            float dx, dy; unpack2(dp, dx, dy);
            float score = fmaf(-2.f, dx + dy, CNs[cbase + c]);
            if (score < best) { best = score; bi = cbase + c; }
        }
        REDs[tid] = best;
        REDi[tid] = bi;
    }
    __syncthreads();

    float ss = 0.f;
    if (tid < 128) {
        int row = tid;
        float lo = REDs[tid];
        int idx = (REDs[tid + 128] < lo) ? REDi[tid + 128] : REDi[tid];
        size_t g = (size_t)(row0 + row) * D_Z;
        #pragma unroll
        for (int q4 = 0; q4 < 4; ++q4) {
            float4 qc = *(const float4*)(CBs + idx*D_Z + q4*4);
            float4 zz = *(const float4*)(ZS + row*20 + q4*4);
            float d0 = qc.x - zz.x, d1 = qc.y - zz.y, d2 = qc.z - zz.z, d3 = qc.w - zz.w;
            ss = fmaf(d0, d0, ss); ss = fmaf(d1, d1, ss);
            ss = fmaf(d2, d2, ss); ss = fmaf(d3, d3, ss);
            *(float4*)(outZq + g + q4*4) = qc;
        }
    }
    __syncthreads();
    if (tid < 128) REDs[tid] = ss;
    __syncthreads();
    #pragma unroll
    for (int s = 64; s > 0; s >>= 1) {
        if (tid < s) REDs[tid] += REDs[tid + s];
        __syncthreads();
    }
    if (tid == 0) g_partial[tile] = REDs[0];
}

__global__ void loss_kernel(float* __restrict__ out_loss)
{
    __shared__ float s[1024];
    float v = 0.f;
    for (int i = threadIdx.x; i < NTILES; i += 1024) v += g_partial[i];
    s[threadIdx.x] = v;
    __syncthreads();
    #pragma unroll
    for (int st = 512; st > 0; st >>= 1) {
        if (threadIdx.x < st) s[threadIdx.x] += s[threadIdx.x + st];
        __syncthreads();
    }
    if (threadIdx.x == 0) {
        float m = s[0] / (float)((long long)N_ROWS * D_Z);
        out_loss[0] = 0.25f * (m + m);   // BETA * (loss_commit + loss_code)
    }
}

extern "C" void kernel_launch(void* const* d_in, const int* in_sizes, int n_in,
                              void* d_out, int out_size)
{
    const float* feats    = (const float*)d_in[0];
    const float* W1       = (const float*)d_in[1];
    const float* b1       = (const float*)d_in[2];
    const float* W2       = (const float*)d_in[3];
    const float* b2       = (const float*)d_in[4];
    const float* Wmu      = (const float*)d_in[5];
    const float* bmu      = (const float*)d_in[6];
    const float* Wlv      = (const float*)d_in[7];
    const float* blv      = (const float*)d_in[8];
    const float* codebook = (const float*)d_in[9];
    const float* eps      = (const float*)d_in[10];

    float* out = (float*)d_out;
    size_t sec = (size_t)N_ROWS * D_Z;

    cudaFuncSetAttribute(enc_kernel, cudaFuncAttributeMaxDynamicSharedMemorySize, SMEM_BYTES);

    enc_kernel<<<NTILES, NTHREADS, SMEM_BYTES>>>(
        feats, W1, b1, W2, b2, Wmu, bmu, Wlv, blv, codebook, eps,
        out,                // z
        out + sec,          // mu
        out + 2 * sec,      // lv
        out + 3 * sec);     // z_q

    loss_kernel<<<1, 1024>>>(out + 4 * sec);
}

// round 3
// speedup vs baseline: 1.1117x; 1.0016x over previous
#include <cuda_runtime.h>
#include <math.h>

#define N_ROWS   524288
#define D_IN     64
#define H_DIM    128
#define D_Z      16
#define K_CODES  256
#define TILE_M   128
#define NTHREADS 256
#define NTILES   (N_ROWS / TILE_M)   // 4096

#define AS 132   // AT row stride (floats)
#define CS 132   // CT row stride (floats)

// ---- shared memory layout (float offsets) ----
#define OFF_AT   0
#define SZ_AT    (D_IN * AS)                 // 8448
#define OFF_CT   (OFF_AT + SZ_AT)            // 8448
#define SZ_CT    (H_DIM * CS)                // 16896
#define OFF_WB   (OFF_CT + SZ_CT)            // 25344
#define SZ_WB    (H_DIM * H_DIM)             // 16384
#define OFF_CB   (OFF_WB + SZ_WB)            // 41728
#define SZ_CB    (K_CODES * D_Z)             // 4096
#define OFF_CN   (OFF_CB + SZ_CB)            // 45824
#define OFF_B1   (OFF_CN + 256)              // 46080
#define OFF_B2   (OFF_B1 + 128)              // 46208
#define OFF_BML  (OFF_B2 + 128)              // 46336
#define OFF_MLB  (OFF_BML + 32)              // 46368
#define SZ_MLB   (TILE_M * 33)               // 4224
#define OFF_ZS   (OFF_MLB + SZ_MLB)          // 50592
#define SZ_ZS    (TILE_M * 20)               // 2560
#define OFF_RED  (OFF_ZS + SZ_ZS)            // 53152
#define OFF_REDI (OFF_RED + 256)             // 53408
#define SMEM_FLOATS (OFF_REDI + 256)         // 53664
#define SMEM_BYTES  (SMEM_FLOATS * 4)        // 214656

typedef unsigned long long u64;

__device__ __forceinline__ u64 bcast2(float x) {
    u64 r; asm("mov.b64 %0, {%1, %1};" : "=l"(r) : "f"(x)); return r;
}
__device__ __forceinline__ u64 pack2(float x, float y) {
    u64 r; asm("mov.b64 %0, {%1, %2};" : "=l"(r) : "f"(x), "f"(y)); return r;
}
__device__ __forceinline__ void unpack2(u64 v, float& x, float& y) {
    asm("mov.b64 {%0, %1}, %2;" : "=f"(x), "=f"(y) : "l"(v));
}
__device__ __forceinline__ void fma2(u64& d, u64 a, u64 b) {
    asm("fma.rn.f32x2 %0, %1, %2, %3;" : "=l"(d) : "l"(a), "l"(b), "l"(d));
}

__device__ float g_partial[NTILES];

__global__ __launch_bounds__(NTHREADS, 1)
void enc_kernel(const float* __restrict__ feats,
                const float* __restrict__ W1,  const float* __restrict__ b1,
                const float* __restrict__ W2,  const float* __restrict__ b2,
                const float* __restrict__ Wmu, const float* __restrict__ bmu,
                const float* __restrict__ Wlv, const float* __restrict__ blv,
                const float* __restrict__ codebook, const float* __restrict__ eps,
                float* __restrict__ outZ,  float* __restrict__ outMu,
                float* __restrict__ outLv, float* __restrict__ outZq)
{
    extern __shared__ float sm[];
    const int tid = threadIdx.x;
    const int tx  = tid & 15;
    const int ty  = tid >> 4;
    const int tile = blockIdx.x;
    const int row0 = tile * TILE_M;

    float* AT   = sm + OFF_AT;
    float* CT   = sm + OFF_CT;
    float* WB   = sm + OFF_WB;
    float* CBs  = sm + OFF_CB;
    float* CNs  = sm + OFF_CN;
    float* B1s  = sm + OFF_B1;
    float* B2s  = sm + OFF_B2;
    float* BMLs = sm + OFF_BML;
    float* MLB  = sm + OFF_MLB;
    float* ZS   = sm + OFF_ZS;
    float* REDs = sm + OFF_RED;
    int*   REDi = (int*)(sm + OFF_REDI);

    // ---------- stage 0: load X (transposed), W1, codebook, biases ----------
    {
        const float4* Xg = (const float4*)(feats + (size_t)row0 * D_IN);
        #pragma unroll
        for (int it = 0; it < 8; ++it) {
            int i = tid + it * NTHREADS;     // 0..2047 float4s
            float4 v = Xg[i];
            int r  = i >> 4;                 // row within tile
            int k0 = (i & 15) << 2;          // starting k
            AT[(k0+0)*AS + r] = v.x;
            AT[(k0+1)*AS + r] = v.y;
            AT[(k0+2)*AS + r] = v.z;
            AT[(k0+3)*AS + r] = v.w;
        }
        const float4* w1 = (const float4*)W1;     // 64*128 = 2048 f4
        #pragma unroll
        for (int it = 0; it < 8; ++it)
            ((float4*)WB)[tid + it*NTHREADS] = w1[tid + it*NTHREADS];
        const float4* cb4 = (const float4*)codebook;  // 256*16 = 1024 f4
        #pragma unroll
        for (int it = 0; it < 4; ++it)
            ((float4*)CBs)[tid + it*NTHREADS] = cb4[tid + it*NTHREADS];
        if (tid < 128) { B1s[tid] = b1[tid]; B2s[tid] = b2[tid]; }
        if (tid < 16)  { BMLs[tid] = bmu[tid]; BMLs[16+tid] = blv[tid]; }
    }
    __syncthreads();

    // codebook norms (one code per thread); consumed only after later syncs
    {
        const float4* c4 = (const float4*)(CBs + tid * D_Z);
        float4 q0 = c4[0], q1 = c4[1], q2 = c4[2], q3 = c4[3];
        float s = q0.x*q0.x + q0.y*q0.y + q0.z*q0.z + q0.w*q0.w
                + q1.x*q1.x + q1.y*q1.y + q1.z*q1.z + q1.w*q1.w
                + q2.x*q2.x + q2.y*q2.y + q2.z*q2.z + q2.w*q2.w
                + q3.x*q3.x + q3.y*q3.y + q3.z*q3.z + q3.w*q3.w;
        CNs[tid] = s;
    }

    const int r0 = ty * 8;
    const int cA = tx * 4;
    const int cB = 64 + tx * 4;

    // packed accumulators: acc2[i][jp] = cols {pair} for row r0+i
    // jp: 0 -> (cA,cA+1), 1 -> (cA+2,cA+3), 2 -> (cB,cB+1), 3 -> (cB+2,cB+3)
    u64 acc2[8][4];
    #pragma unroll
    for (int i = 0; i < 8; ++i)
        #pragma unroll
        for (int j = 0; j < 4; ++j) acc2[i][j] = 0ULL;

    // ---------- GEMM1: h1 = relu(X @ W1 + b1) ----------
    #pragma unroll 4
    for (int k = 0; k < D_IN; ++k) {
        float4 a0 = *(const float4*)(AT + k*AS + r0);
        float4 a1 = *(const float4*)(AT + k*AS + r0 + 4);
        ulonglong2 bq0 = *(const ulonglong2*)(WB + k*H_DIM + cA);
        ulonglong2 bq1 = *(const ulonglong2*)(WB + k*H_DIM + cB);
        u64 bp0 = bq0.x, bp1 = bq0.y, bp2 = bq1.x, bp3 = bq1.y;
        float av[8] = {a0.x,a0.y,a0.z,a0.w,a1.x,a1.y,a1.z,a1.w};
        #pragma unroll
        for (int i = 0; i < 8; ++i) {
            u64 aa = bcast2(av[i]);
            fma2(acc2[i][0], aa, bp0);
            fma2(acc2[i][1], aa, bp1);
            fma2(acc2[i][2], aa, bp2);
            fma2(acc2[i][3], aa, bp3);
        }
    }
    // epilogue: relu(acc + b1) -> CT (stored transposed: CT[col][row])
    #pragma unroll
    for (int jp = 0; jp < 4; ++jp) {
        int c0 = (jp < 2) ? (cA + 2*jp) : (cB + 2*(jp-2));
        float bias0 = B1s[c0], bias1 = B1s[c0+1];
        float v0[8], v1[8];
        #pragma unroll
        for (int i = 0; i < 8; ++i) {
            float x, y; unpack2(acc2[i][jp], x, y);
            v0[i] = fmaxf(x + bias0, 0.f);
            v1[i] = fmaxf(y + bias1, 0.f);
        }
        *(float4*)(CT + c0*CS + r0)       = make_float4(v0[0],v0[1],v0[2],v0[3]);
        *(float4*)(CT + c0*CS + r0 + 4)   = make_float4(v0[4],v0[5],v0[6],v0[7]);
        *(float4*)(CT + (c0+1)*CS + r0)     = make_float4(v1[0],v1[1],v1[2],v1[3]);
        *(float4*)(CT + (c0+1)*CS + r0 + 4) = make_float4(v1[4],v1[5],v1[6],v1[7]);
    }
    __syncthreads();

    // load W2 (overwrites W1)
    {
        const float4* w2 = (const float4*)W2;    // 128*128 = 4096 f4
        #pragma unroll
        for (int it = 0; it < 16; ++it)
            ((float4*)WB)[tid + it*NTHREADS] = w2[tid + it*NTHREADS];
    }
    __syncthreads();

    // ---------- GEMM2: h2 = relu(h1 @ W2 + b2) ----------
    #pragma unroll
    for (int i = 0; i < 8; ++i)
        #pragma unroll
        for (int j = 0; j < 4; ++j) acc2[i][j] = 0ULL;

    #pragma unroll 4
    for (int k = 0; k < H_DIM; ++k) {
        float4 a0 = *(const float4*)(CT + k*CS + r0);
        float4 a1 = *(const float4*)(CT + k*CS + r0 + 4);
        ulonglong2 bq0 = *(const ulonglong2*)(WB + k*H_DIM + cA);
        ulonglong2 bq1 = *(const ulonglong2*)(WB + k*H_DIM + cB);
        u64 bp0 = bq0.x, bp1 = bq0.y, bp2 = bq1.x, bp3 = bq1.y;
        float av[8] = {a0.x,a0.y,a0.z,a0.w,a1.x,a1.y,a1.z,a1.w};
        #pragma unroll
        for (int i = 0; i < 8; ++i) {
            u64 aa = bcast2(av[i]);
            fma2(acc2[i][0], aa, bp0);
            fma2(acc2[i][1], aa, bp1);
            fma2(acc2[i][2], aa, bp2);
            fma2(acc2[i][3], aa, bp3);
        }
    }
    __syncthreads();   // all reads of CT(h1) + WB(W2) done

    // epilogue: h2 -> CT (overwrite); load Wmu|Wlv -> WB[k*32 + c]
    #pragma unroll
    for (int jp = 0; jp < 4; ++jp) {
        int c0 = (jp < 2) ? (cA + 2*jp) : (cB + 2*(jp-2));
        float bias0 = B2s[c0], bias1 = B2s[c0+1];
        float v0[8], v1[8];
        #pragma unroll
        for (int i = 0; i < 8; ++i) {
            float x, y; unpack2(acc2[i][jp], x, y);
            v0[i] = fmaxf(x + bias0, 0.f);
            v1[i] = fmaxf(y + bias1, 0.f);
        }
        *(float4*)(CT + c0*CS + r0)       = make_float4(v0[0],v0[1],v0[2],v0[3]);
        *(float4*)(CT + c0*CS + r0 + 4)   = make_float4(v0[4],v0[5],v0[6],v0[7]);
        *(float4*)(CT + (c0+1)*CS + r0)     = make_float4(v1[0],v1[1],v1[2],v1[3]);
        *(float4*)(CT + (c0+1)*CS + r0 + 4) = make_float4(v1[4],v1[5],v1[6],v1[7]);
    }
    {
        #pragma unroll
        for (int it = 0; it < 2; ++it) {
            int i = tid + it*NTHREADS;          // 0..511 f4 (128*16 floats)
            float4 v = ((const float4*)Wmu)[i];
            float4 u = ((const float4*)Wlv)[i];
            int k  = i >> 2;
            int c0 = (i & 3) << 2;
            *(float4*)(WB + k*32 + c0)      = v;
            *(float4*)(WB + k*32 + 16 + c0) = u;
        }
    }
    __syncthreads();

    // ---------- GEMM3: [mu | lv] = h2 @ [Wmu | Wlv] + [bmu | blv] ----------
    u64 acc3[8];
    #pragma unroll
    for (int i = 0; i < 8; ++i) acc3[i] = 0ULL;

    const int c3 = 2 * tx;   // even -> 8-byte aligned pair in WB
    #pragma unroll 4
    for (int k = 0; k < H_DIM; ++k) {
        float4 a0 = *(const float4*)(CT + k*CS + r0);
        float4 a1 = *(const float4*)(CT + k*CS + r0 + 4);
        u64 wp = *(const u64*)(WB + k*32 + c3);
        float av[8] = {a0.x,a0.y,a0.z,a0.w,a1.x,a1.y,a1.z,a1.w};
        #pragma unroll
        for (int i = 0; i < 8; ++i) {
            u64 aa = bcast2(av[i]);
            fma2(acc3[i], aa, wp);
        }
    }
    // epilogue: write mu/lv to smem MLB and to global
    {
        float bias0 = BMLs[c3], bias1 = BMLs[c3 + 1];
        float* g0 = (c3 < D_Z) ? (outMu + c3) : (outLv + (c3 - D_Z));
        float* g1 = (c3 + 1 < D_Z) ? (outMu + c3 + 1) : (outLv + (c3 + 1 - D_Z));
        #pragma unroll
        for (int i = 0; i < 8; ++i) {
            float x, y; unpack2(acc3[i], x, y);
            x += bias0; y += bias1;
            MLB[(r0 + i)*33 + c3]     = x;
            MLB[(r0 + i)*33 + c3 + 1] = y;
            g0[(size_t)(row0 + r0 + i) * D_Z] = x;
            g1[(size_t)(row0 + r0 + i) * D_Z] = y;
        }
    }
    __syncthreads();

    // ---------- z = mu + eps * exp(0.5*lv) ----------
    {
        int row = tid >> 1;
        int d0  = (tid & 1) << 3;
        size_t g = (size_t)(row0 + row) * D_Z + d0;
        float4 e0 = *(const float4*)(eps + g);
        float4 e1 = *(const float4*)(eps + g + 4);
        float ev[8] = {e0.x,e0.y,e0.z,e0.w,e1.x,e1.y,e1.z,e1.w};
        float zv[8];
        #pragma unroll
        for (int q = 0; q < 8; ++q) {
            float mu = MLB[row*33 + d0 + q];
            float lv = MLB[row*33 + 16 + d0 + q];
            zv[q] = fmaf(ev[q], expf(0.5f * lv), mu);
        }
        *(float4*)(ZS + row*20 + d0)     = make_float4(zv[0],zv[1],zv[2],zv[3]);
        *(float4*)(ZS + row*20 + d0 + 4) = make_float4(zv[4],zv[5],zv[6],zv[7]);
        *(float4*)(outZ + g)     = make_float4(zv[0],zv[1],zv[2],zv[3]);
        *(float4*)(outZ + g + 4) = make_float4(zv[4],zv[5],zv[6],zv[7]);
    }
    __syncthreads();

    // ---------- VQ argmin: score = |c|^2 - 2 z.c (|z|^2 constant per row) ----------
    {
        int row  = tid & 127;
        int half = tid >> 7;
        // z as 8 packed pairs (ZS row base is 8-byte aligned: 20 floats stride)
        u64 zp[8];
        #pragma unroll
        for (int q = 0; q < 8; ++q)
            zp[q] = *(const u64*)(ZS + row*20 + 2*q);
        float best = 3.4e38f;
        int   bi   = 0;
        int cbase = half << 7;
        for (int c = 0; c < 128; ++c) {
            const ulonglong2* q2 = (const ulonglong2*)(CBs + (cbase + c) * D_Z);
            ulonglong2 qa = q2[0], qb = q2[1];
            u64 dp = 0ULL;
            fma2(dp, zp[0], qa.x);
            fma2(dp, zp[1], qa.y);
            fma2(dp, zp[2], qb.x);
            fma2(dp, zp[3], qb.y);
            ulonglong2 qc = q2[2], qd = q2[3];
            fma2(dp, zp[4], qc.x);
            fma2(dp, zp[5], qc.y);
            fma2(dp, zp[6], qd.x);
            fma2(dp, zp[7], qd.y);
            float dx, dy; unpack2(dp, dx, dy);
            float score = fmaf(-2.f, dx + dy, CNs[cbase + c]);
            if (score < best) { best = score; bi = cbase + c; }
        }
        REDs[tid] = best;
        REDi[tid] = bi;
    }
    __syncthreads();

    float ss = 0.f;
    if (tid < 128) {
        int row = tid;
        float lo = REDs[tid];
        int idx = (REDs[tid + 128] < lo) ? REDi[tid + 128] : REDi[tid];
        size_t g = (size_t)(row0 + row) * D_Z;
        #pragma unroll
        for (int q4 = 0; q4 < 4; ++q4) {
            float4 qc = *(const float4*)(CBs + idx*D_Z + q4*4);
            float4 zz = *(const float4*)(ZS + row*20 + q4*4);
            float d0 = qc.x - zz.x, d1 = qc.y - zz.y, d2 = qc.z - zz.z, d3 = qc.w - zz.w;
            ss = fmaf(d0, d0, ss); ss = fmaf(d1, d1, ss);
            ss = fmaf(d2, d2, ss); ss = fmaf(d3, d3, ss);
            *(float4*)(outZq + g + q4*4) = qc;
        }
    }
    __syncthreads();
    if (tid < 128) REDs[tid] = ss;
    __syncthreads();
    #pragma unroll
    for (int s = 64; s > 0; s >>= 1) {
        if (tid < s) REDs[tid] += REDs[tid + s];
        __syncthreads();
    }
    if (tid == 0) g_partial[tile] = REDs[0];
}

__global__ void loss_kernel(float* __restrict__ out_loss)
{
    __shared__ float s[1024];
    float v = 0.f;
    for (int i = threadIdx.x; i < NTILES; i += 1024) v += g_partial[i];
    s[threadIdx.x] = v;
    __syncthreads();
    #pragma unroll
    for (int st = 512; st > 0; st >>= 1) {
        if (threadIdx.x < st) s[threadIdx.x] += s[threadIdx.x + st];
        __syncthreads();
    }
    if (threadIdx.x == 0) {
        float m = s[0] / (float)((long long)N_ROWS * D_Z);
        out_loss[0] = 0.25f * (m + m);   // BETA * (loss_commit + loss_code)
    }
}

extern "C" void kernel_launch(void* const* d_in, const int* in_sizes, int n_in,
                              void* d_out, int out_size)
{
    const float* feats    = (const float*)d_in[0];
    const float* W1       = (const float*)d_in[1];
    const float* b1       = (const float*)d_in[2];
    const float* W2       = (const float*)d_in[3];
    const float* b2       = (const float*)d_in[4];
    const float* Wmu      = (const float*)d_in[5];
    const float* bmu      = (const float*)d_in[6];
    const float* Wlv      = (const float*)d_in[7];
    const float* blv      = (const float*)d_in[8];
    const float* codebook = (const float*)d_in[9];
    const float* eps      = (const float*)d_in[10];

    float* out = (float*)d_out;
    size_t sec = (size_t)N_ROWS * D_Z;

    cudaFuncSetAttribute(enc_kernel, cudaFuncAttributeMaxDynamicSharedMemorySize, SMEM_BYTES);

    enc_kernel<<<NTILES, NTHREADS, SMEM_BYTES>>>(
        feats, W1, b1, W2, b2, Wmu, bmu, Wlv, blv, codebook, eps,
        out,                // z
        out + sec,          // mu
        out + 2 * sec,      // lv
        out + 3 * sec);     // z_q

    loss_kernel<<<1, 1024>>>(out + 4 * sec);
}

// round 7
// speedup vs baseline: 1.1391x; 1.0246x over previous
#include <cuda_runtime.h>
#include <math.h>
#include <stdint.h>

#define N_ROWS   524288
#define D_IN     64
#define H_DIM    128
#define D_Z      16
#define K_CODES  256
#define TILE_M   128
#define NTHREADS 256
#define NTILES   (N_ROWS / TILE_M)   // 4096

#define AS 132   // AT row stride (floats)
#define CS 132   // CT row stride (floats)

// ---- shared memory layout (float offsets) ----
// AT region [0,8448) used only during GEMM1; aliased afterward:
//   CB (codebook, 4096 f) @ 0 ; W3 ([k][32] packed Wmu|Wlv, 4096 f) @ 4096
#define OFF_AT   0
#define SZ_AT    (D_IN * AS)                 // 8448
#define OFF_CB   0
#define OFF_W3   4096
#define OFF_CT   (OFF_AT + SZ_AT)            // 8448
#define SZ_CT    (H_DIM * CS)                // 16896
#define OFF_W    (OFF_CT + SZ_CT)            // 25344 : [W1|W2h1 (8192)] [W2h0 (8192)]
#define SZ_W     16384
#define OFF_CN   (OFF_W + SZ_W)              // 41728
#define OFF_B1   (OFF_CN + 256)              // 41984
#define OFF_B2   (OFF_B1 + 128)              // 42112
#define OFF_BML  (OFF_B2 + 128)              // 42240
#define OFF_MLB  (OFF_BML + 32)              // 42272
#define SZ_MLB   (TILE_M * 33)               // 4224
#define OFF_ZS   (OFF_MLB + SZ_MLB)          // 46496
#define SZ_ZS    (TILE_M * 20)               // 2560
#define OFF_RED  (OFF_ZS + SZ_ZS)            // 49056
#define OFF_REDI (OFF_RED + 256)             // 49312
#define SMEM_FLOATS (OFF_REDI + 256)         // 49568
#define SMEM_BYTES  (SMEM_FLOATS * 4)        // 198272

typedef unsigned long long u64;

__device__ __forceinline__ u64 bcast2(float x) {
    u64 r; asm("mov.b64 %0, {%1, %1};" : "=l"(r) : "f"(x)); return r;
}
__device__ __forceinline__ void unpack2(u64 v, float& x, float& y) {
    asm("mov.b64 {%0, %1}, %2;" : "=f"(x), "=f"(y) : "l"(v));
}
__device__ __forceinline__ void fma2(u64& d, u64 a, u64 b) {
    asm("fma.rn.f32x2 %0, %1, %2, %3;" : "=l"(d) : "l"(a), "l"(b), "l"(d));
}
__device__ __forceinline__ uint32_t smem_u32(const void* p) {
    uint32_t a;
    asm("{ .reg .u64 t; cvta.to.shared.u64 t, %1; cvt.u32.u64 %0, t; }" : "=r"(a) : "l"(p));
    return a;
}
__device__ __forceinline__ void cp16(uint32_t dst, const void* src) {
    asm volatile("cp.async.cg.shared.global [%0], [%1], 16;" :: "r"(dst), "l"(src) : "memory");
}
#define CP_COMMIT() asm volatile("cp.async.commit_group;" ::: "memory")
#define CP_WAIT0()  asm volatile("cp.async.wait_group 0;" ::: "memory")
#define CP_WAIT1()  asm volatile("cp.async.wait_group 1;" ::: "memory")

__device__ float g_partial[NTILES];

__global__ __launch_bounds__(NTHREADS, 1)
void enc_kernel(const float* __restrict__ feats,
                const float* __restrict__ W1,  const float* __restrict__ b1,
                const float* __restrict__ W2,  const float* __restrict__ b2,
                const float* __restrict__ Wmu, const float* __restrict__ bmu,
                const float* __restrict__ Wlv, const float* __restrict__ blv,
                const float* __restrict__ codebook, const float* __restrict__ eps,
                float* __restrict__ outZ,  float* __restrict__ outMu,
                float* __restrict__ outLv, float* __restrict__ outZq)
{
    extern __shared__ float sm[];
    const uint32_t sb = smem_u32(sm);
    const int tid = threadIdx.x;
    const int tx  = tid & 15;
    const int ty  = tid >> 4;
    const int tile = blockIdx.x;
    const int row0 = tile * TILE_M;

    float* AT   = sm + OFF_AT;
    float* CBs  = sm + OFF_CB;
    float* W3s  = sm + OFF_W3;
    float* CT   = sm + OFF_CT;
    float* WB   = sm + OFF_W;          // W1 now; W2h1 later
    float* WBh0 = sm + OFF_W + 8192;   // W2h0
    float* CNs  = sm + OFF_CN;
    float* B1s  = sm + OFF_B1;
    float* B2s  = sm + OFF_B2;
    float* BMLs = sm + OFF_BML;
    float* MLB  = sm + OFF_MLB;
    float* ZS   = sm + OFF_ZS;
    float* REDs = sm + OFF_RED;
    int*   REDi = (int*)(sm + OFF_REDI);

    // ---------- phase 0: cp.async W1 + W2h0 ; X transpose ; biases ----------
    {
        // W1: 8192 floats -> OFF_W ; W2h0: first 8192 floats of W2 -> OFF_W+8192
        #pragma unroll
        for (int it = 0; it < 8; ++it) {
            int i = tid + it * NTHREADS;   // 0..2047 chunks of 16B
            cp16(sb + (OFF_W << 2) + i * 16, W1 + i * 4);
            cp16(sb + ((OFF_W + 8192) << 2) + i * 16, W2 + i * 4);
        }
        CP_COMMIT();

        const float4* Xg = (const float4*)(feats + (size_t)row0 * D_IN);
        #pragma unroll
        for (int it = 0; it < 8; ++it) {
            int i = tid + it * NTHREADS;     // 0..2047 float4s
            float4 v = Xg[i];
            int r  = i >> 4;
            int k0 = (i & 15) << 2;
            AT[(k0+0)*AS + r] = v.x;
            AT[(k0+1)*AS + r] = v.y;
            AT[(k0+2)*AS + r] = v.z;
            AT[(k0+3)*AS + r] = v.w;
        }
        if (tid < 128) { B1s[tid] = b1[tid]; B2s[tid] = b2[tid]; }
        if (tid < 16)  { BMLs[tid] = bmu[tid]; BMLs[16+tid] = blv[tid]; }
    }
    CP_WAIT0();
    __syncthreads();

    const int r0 = ty * 8;
    const int cA = tx * 4;
    const int cB = 64 + tx * 4;

    u64 acc2[8][4];
    #pragma unroll
    for (int i = 0; i < 8; ++i)
        #pragma unroll
        for (int j = 0; j < 4; ++j) acc2[i][j] = 0ULL;

    // ---------- GEMM1: h1 = relu(X @ W1 + b1) ----------
    #pragma unroll 4
    for (int k = 0; k < D_IN; ++k) {
        float4 a0 = *(const float4*)(AT + k*AS + r0);
        float4 a1 = *(const float4*)(AT + k*AS + r0 + 4);
        ulonglong2 bq0 = *(const ulonglong2*)(WB + k*H_DIM + cA);
        ulonglong2 bq1 = *(const ulonglong2*)(WB + k*H_DIM + cB);
        u64 bp0 = bq0.x, bp1 = bq0.y, bp2 = bq1.x, bp3 = bq1.y;
        float av[8] = {a0.x,a0.y,a0.z,a0.w,a1.x,a1.y,a1.z,a1.w};
        #pragma unroll
        for (int i = 0; i < 8; ++i) {
            u64 aa = bcast2(av[i]);
            fma2(acc2[i][0], aa, bp0);
            fma2(acc2[i][1], aa, bp1);
            fma2(acc2[i][2], aa, bp2);
            fma2(acc2[i][3], aa, bp3);
        }
    }
    // epilogue: relu(acc + b1) -> CT (transposed)
    #pragma unroll
    for (int jp = 0; jp < 4; ++jp) {
        int c0 = (jp < 2) ? (cA + 2*jp) : (cB + 2*(jp-2));
        float bias0 = B1s[c0], bias1 = B1s[c0+1];
        float v0[8], v1[8];
        #pragma unroll
        for (int i = 0; i < 8; ++i) {
            float x, y; unpack2(acc2[i][jp], x, y);
            v0[i] = fmaxf(x + bias0, 0.f);
            v1[i] = fmaxf(y + bias1, 0.f);
        }
        *(float4*)(CT + c0*CS + r0)         = make_float4(v0[0],v0[1],v0[2],v0[3]);
        *(float4*)(CT + c0*CS + r0 + 4)     = make_float4(v0[4],v0[5],v0[6],v0[7]);
        *(float4*)(CT + (c0+1)*CS + r0)     = make_float4(v1[0],v1[1],v1[2],v1[3]);
        *(float4*)(CT + (c0+1)*CS + r0 + 4) = make_float4(v1[4],v1[5],v1[6],v1[7]);
    }
    __syncthreads();   // all GEMM1 reads of AT + WB(W1) done

    // ---------- overlap: cp.async W2h1 -> WB ; CB + W3 -> AT region ----------
    {
        #pragma unroll
        for (int it = 0; it < 8; ++it) {
            int i = tid + it * NTHREADS;   // 0..2047
            cp16(sb + (OFF_W << 2) + i * 16, W2 + 8192 + i * 4);
        }
        CP_COMMIT();   // group: W2h1
        #pragma unroll
        for (int it = 0; it < 4; ++it) {
            int i = tid + it * NTHREADS;   // 0..1023
            cp16(sb + (OFF_CB << 2) + i * 16, codebook + i * 4);
        }
        #pragma unroll
        for (int it = 0; it < 4; ++it) {
            int i = tid + it * NTHREADS;   // 0..1023 : W3 pack [k][32]
            int k = i >> 3, c = i & 7;
            uint32_t dst = sb + (OFF_W3 << 2) + (k * 32 + ((c & 3) << 2) + ((c >> 2) << 4)) * 4;
            const float* src = (c < 4) ? (Wmu + k * 16 + ((c & 3) << 2))
                                       : (Wlv + k * 16 + ((c & 3) << 2));
            cp16(dst, src);
        }
        CP_COMMIT();   // group: CB + W3
    }

    // ---------- GEMM2 half0 (k 0..63 from WBh0) ----------
    #pragma unroll
    for (int i = 0; i < 8; ++i)
        #pragma unroll
        for (int j = 0; j < 4; ++j) acc2[i][j] = 0ULL;

    #pragma unroll 4
    for (int k = 0; k < 64; ++k) {
        float4 a0 = *(const float4*)(CT + k*CS + r0);
        float4 a1 = *(const float4*)(CT + k*CS + r0 + 4);
        ulonglong2 bq0 = *(const ulonglong2*)(WBh0 + k*H_DIM + cA);
        ulonglong2 bq1 = *(const ulonglong2*)(WBh0 + k*H_DIM + cB);
        u64 bp0 = bq0.x, bp1 = bq0.y, bp2 = bq1.x, bp3 = bq1.y;
        float av[8] = {a0.x,a0.y,a0.z,a0.w,a1.x,a1.y,a1.z,a1.w};
        #pragma unroll
        for (int i = 0; i < 8; ++i) {
            u64 aa = bcast2(av[i]);
            fma2(acc2[i][0], aa, bp0);
            fma2(acc2[i][1], aa, bp1);
            fma2(acc2[i][2], aa, bp2);
            fma2(acc2[i][3], aa, bp3);
        }
    }
    CP_WAIT1();        // W2h1 arrived (CB+W3 may still be in flight)
    __syncthreads();

    // ---------- GEMM2 half1 (k 64..127 from WB) ----------
    #pragma unroll 4
    for (int k = 64; k < 128; ++k) {
        float4 a0 = *(const float4*)(CT + k*CS + r0);
        float4 a1 = *(const float4*)(CT + k*CS + r0 + 4);
        ulonglong2 bq0 = *(const ulonglong2*)(WB + (k-64)*H_DIM + cA);
        ulonglong2 bq1 = *(const ulonglong2*)(WB + (k-64)*H_DIM + cB);
        u64 bp0 = bq0.x, bp1 = bq0.y, bp2 = bq1.x, bp3 = bq1.y;
        float av[8] = {a0.x,a0.y,a0.z,a0.w,a1.x,a1.y,a1.z,a1.w};
        #pragma unroll
        for (int i = 0; i < 8; ++i) {
            u64 aa = bcast2(av[i]);
            fma2(acc2[i][0], aa, bp0);
            fma2(acc2[i][1], aa, bp1);
            fma2(acc2[i][2], aa, bp2);
            fma2(acc2[i][3], aa, bp3);
        }
    }
    __syncthreads();   // all reads of CT(h1) done

    // epilogue: h2 -> CT (overwrite)
    #pragma unroll
    for (int jp = 0; jp < 4; ++jp) {
        int c0 = (jp < 2) ? (cA + 2*jp) : (cB + 2*(jp-2));
        float bias0 = B2s[c0], bias1 = B2s[c0+1];
        float v0[8], v1[8];
        #pragma unroll
        for (int i = 0; i < 8; ++i) {
            float x, y; unpack2(acc2[i][jp], x, y);
            v0[i] = fmaxf(x + bias0, 0.f);
            v1[i] = fmaxf(y + bias1, 0.f);
        }
        *(float4*)(CT + c0*CS + r0)         = make_float4(v0[0],v0[1],v0[2],v0[3]);
        *(float4*)(CT + c0*CS + r0 + 4)     = make_float4(v0[4],v0[5],v0[6],v0[7]);
        *(float4*)(CT + (c0+1)*CS + r0)     = make_float4(v1[0],v1[1],v1[2],v1[3]);
        *(float4*)(CT + (c0+1)*CS + r0 + 4) = make_float4(v1[4],v1[5],v1[6],v1[7]);
    }
    CP_WAIT0();        // CB + W3 arrived
    __syncthreads();

    // codebook norms (one code per thread)
    {
        const float4* c4 = (const float4*)(CBs + tid * D_Z);
        float4 q0 = c4[0], q1 = c4[1], q2 = c4[2], q3 = c4[3];
        CNs[tid] = q0.x*q0.x + q0.y*q0.y + q0.z*q0.z + q0.w*q0.w
                 + q1.x*q1.x + q1.y*q1.y + q1.z*q1.z + q1.w*q1.w
                 + q2.x*q2.x + q2.y*q2.y + q2.z*q2.z + q2.w*q2.w
                 + q3.x*q3.x + q3.y*q3.y + q3.z*q3.z + q3.w*q3.w;
    }

    // ---------- GEMM3: [mu | lv] = h2 @ [Wmu | Wlv] + [bmu | blv] ----------
    u64 acc3[8];
    #pragma unroll
    for (int i = 0; i < 8; ++i) acc3[i] = 0ULL;

    const int c3 = 2 * tx;
    #pragma unroll 4
    for (int k = 0; k < H_DIM; ++k) {
        float4 a0 = *(const float4*)(CT + k*CS + r0);
        float4 a1 = *(const float4*)(CT + k*CS + r0 + 4);
        u64 wp = *(const u64*)(W3s + k*32 + c3);
        float av[8] = {a0.x,a0.y,a0.z,a0.w,a1.x,a1.y,a1.z,a1.w};
        #pragma unroll
        for (int i = 0; i < 8; ++i) {
            u64 aa = bcast2(av[i]);
            fma2(acc3[i], aa, wp);
        }
    }
    // epilogue: mu/lv -> MLB + global
    {
        float bias0 = BMLs[c3], bias1 = BMLs[c3 + 1];
        float* g0 = (c3 < D_Z) ? (outMu + c3) : (outLv + (c3 - D_Z));
        float* g1 = (c3 + 1 < D_Z) ? (outMu + c3 + 1) : (outLv + (c3 + 1 - D_Z));
        #pragma unroll
        for (int i = 0; i < 8; ++i) {
            float x, y; unpack2(acc3[i], x, y);
            x += bias0; y += bias1;
            MLB[(r0 + i)*33 + c3]     = x;
            MLB[(r0 + i)*33 + c3 + 1] = y;
            g0[(size_t)(row0 + r0 + i) * D_Z] = x;
            g1[(size_t)(row0 + r0 + i) * D_Z] = y;
        }
    }
    __syncthreads();

    // ---------- z = mu + eps * exp(0.5*lv) ----------
    {
        int row = tid >> 1;
        int d0  = (tid & 1) << 3;
        size_t g = (size_t)(row0 + row) * D_Z + d0;
        float4 e0 = *(const float4*)(eps + g);
        float4 e1 = *(const float4*)(eps + g + 4);
        float ev[8] = {e0.x,e0.y,e0.z,e0.w,e1.x,e1.y,e1.z,e1.w};
        float zv[8];
        #pragma unroll
        for (int q = 0; q < 8; ++q) {
            float mu = MLB[row*33 + d0 + q];
            float lv = MLB[row*33 + 16 + d0 + q];
            zv[q] = fmaf(ev[q], expf(0.5f * lv), mu);
        }
        *(float4*)(ZS + row*20 + d0)     = make_float4(zv[0],zv[1],zv[2],zv[3]);
        *(float4*)(ZS + row*20 + d0 + 4) = make_float4(zv[4],zv[5],zv[6],zv[7]);
        *(float4*)(outZ + g)     = make_float4(zv[0],zv[1],zv[2],zv[3]);
        *(float4*)(outZ + g + 4) = make_float4(zv[4],zv[5],zv[6],zv[7]);
    }
    __syncthreads();

    // ---------- VQ argmin: score = |c|^2 - 2 z.c ----------
    {
        int row  = tid & 127;
        int half = tid >> 7;
        u64 zp[8];
        #pragma unroll
        for (int q = 0; q < 8; ++q)
            zp[q] = *(const u64*)(ZS + row*20 + 2*q);
        float best = 3.4e38f;
        int   bi   = 0;
        int cbase = half << 7;
        for (int c = 0; c < 128; ++c) {
            const ulonglong2* q2 = (const ulonglong2*)(CBs + (cbase + c) * D_Z);
            ulonglong2 qa = q2[0], qb = q2[1];
            u64 dp = 0ULL;
            fma2(dp, zp[0], qa.x);
            fma2(dp, zp[1], qa.y);
            fma2(dp, zp[2], qb.x);
            fma2(dp, zp[3], qb.y);
            ulonglong2 qc = q2[2], qd = q2[3];
            fma2(dp, zp[4], qc.x);
            fma2(dp, zp[5], qc.y);
            fma2(dp, zp[6], qd.x);
            fma2(dp, zp[7], qd.y);
            float dx, dy; unpack2(dp, dx, dy);
            float score = fmaf(-2.f, dx + dy, CNs[cbase + c]);
            if (score < best) { best = score; bi = cbase + c; }
        }
        REDs[tid] = best;
        REDi[tid] = bi;
    }
    __syncthreads();

    float ss = 0.f;
    if (tid < 128) {
        int row = tid;
        float lo = REDs[tid];
        int idx = (REDs[tid + 128] < lo) ? REDi[tid + 128] : REDi[tid];
        size_t g = (size_t)(row0 + row) * D_Z;
        #pragma unroll
        for (int q4 = 0; q4 < 4; ++q4) {
            float4 qc = *(const float4*)(CBs + idx*D_Z + q4*4);
            float4 zz = *(const float4*)(ZS + row*20 + q4*4);
            float d0 = qc.x - zz.x, d1 = qc.y - zz.y, d2 = qc.z - zz.z, d3 = qc.w - zz.w;
            ss = fmaf(d0, d0, ss); ss = fmaf(d1, d1, ss);
            ss = fmaf(d2, d2, ss); ss = fmaf(d3, d3, ss);
            *(float4*)(outZq + g + q4*4) = qc;
        }
    }
    __syncthreads();
    if (tid < 128) REDs[tid] = ss;
    __syncthreads();
    #pragma unroll
    for (int s = 64; s > 0; s >>= 1) {
        if (tid < s) REDs[tid] += REDs[tid + s];
        __syncthreads();
    }
    if (tid == 0) g_partial[tile] = REDs[0];
}

__global__ void loss_kernel(float* __restrict__ out_loss)
{
    __shared__ float s[1024];
    float v = 0.f;
    for (int i = threadIdx.x; i < NTILES; i += 1024) v += g_partial[i];
    s[threadIdx.x] = v;
    __syncthreads();
    #pragma unroll
    for (int st = 512; st > 0; st >>= 1) {
        if (threadIdx.x < st) s[threadIdx.x] += s[threadIdx.x + st];
        __syncthreads();
    }
    if (threadIdx.x == 0) {
        float m = s[0] / (float)((long long)N_ROWS * D_Z);
        out_loss[0] = 0.25f * (m + m);   // BETA * (loss_commit + loss_code)
    }
}

extern "C" void kernel_launch(void* const* d_in, const int* in_sizes, int n_in,
                              void* d_out, int out_size)
{
    const float* feats    = (const float*)d_in[0];
    const float* W1       = (const float*)d_in[1];
    const float* b1       = (const float*)d_in[2];
    const float* W2       = (const float*)d_in[3];
    const float* b2       = (const float*)d_in[4];
    const float* Wmu      = (const float*)d_in[5];
    const float* bmu      = (const float*)d_in[6];
    const float* Wlv      = (const float*)d_in[7];
    const float* blv      = (const float*)d_in[8];
    const float* codebook = (const float*)d_in[9];
    const float* eps      = (const float*)d_in[10];

    float* out = (float*)d_out;
    size_t sec = (size_t)N_ROWS * D_Z;

    cudaFuncSetAttribute(enc_kernel, cudaFuncAttributeMaxDynamicSharedMemorySize, SMEM_BYTES);

    enc_kernel<<<NTILES, NTHREADS, SMEM_BYTES>>>(
        feats, W1, b1, W2, b2, Wmu, bmu, Wlv, blv, codebook, eps,
        out,                // z
        out + sec,          // mu
        out + 2 * sec,      // lv
        out + 3 * sec);     // z_q

    loss_kernel<<<1, 1024>>>(out + 4 * sec);
}